// round 2
// baseline (speedup 1.0000x reference)
#include <cuda_runtime.h>
#include <cstdint>

// ============================================================================
// QuantizedLinear: out = scale * (x @ S^T) + bias, S = sign(w)*(|w|>0.7*mean|w|)
// x [65536, 512] fp32, w [512, 512] fp32, bias [512] fp32, out [65536, 512] fp32
//
// Toolchain note: PTX stage targets compute_103 (non-'a'), so tcgen05/TMEM are
// unavailable. Use classic mma.sync.m16n8k8.tf32 (HMMA path) + cp.async.
// ============================================================================
#define K_DIM 512
#define N_DIM 512
#define BM 128
#define BN 64
#define BK 32
#define KT (K_DIM / BK)      // 16
#define STAGES 4
#define PAD_K 36             // 32 + 4 pad -> conflict-free LDS
#define THREADS 256

#define A_STAGE_BYTES (BM * PAD_K * 4)           // 18432
#define B_STAGE_BYTES (BN * PAD_K * 4)           // 9216
#define STAGE_BYTES   (A_STAGE_BYTES + B_STAGE_BYTES)
#define SMEM_TOTAL    (STAGES * STAGE_BYTES)     // 110592

// Scratch (allocation-free)
__device__ float  d_wq[N_DIM * K_DIM];
__device__ double d_partial[256];
__device__ float  d_scale;
__device__ float  d_thresh;

// ============================================================================
// Prep: scale = max(mean|w|, 1e-8); thresh = 0.7*scale; S = sign(w)*(|w|>t)
// ============================================================================
__global__ void k_abssum(const float* __restrict__ w) {
    __shared__ double s[256];
    int b = blockIdx.x, t = threadIdx.x;
    const float* p = w + b * 1024;
    double acc = (double)fabsf(p[t]) + (double)fabsf(p[t + 256]) +
                 (double)fabsf(p[t + 512]) + (double)fabsf(p[t + 768]);
    s[t] = acc;
    __syncthreads();
    for (int o = 128; o > 0; o >>= 1) {
        if (t < o) s[t] += s[t + o];
        __syncthreads();
    }
    if (t == 0) d_partial[b] = s[0];
}

__global__ void k_scale() {
    double tot = 0.0;
    for (int i = 0; i < 256; i++) tot += d_partial[i];
    float sc = (float)(tot / (double)(N_DIM * K_DIM));
    if (sc < 1e-8f) sc = 1e-8f;
    d_scale = sc;
    d_thresh = 0.7f * sc;
}

__global__ void k_quant(const float* __restrict__ w) {
    int i = blockIdx.x * blockDim.x + threadIdx.x;
    float v = w[i];
    float th = d_thresh;
    d_wq[i] = (fabsf(v) > th) ? (v > 0.0f ? 1.0f : -1.0f) : 0.0f;
}

// ============================================================================
// Helpers
// ============================================================================
__device__ __forceinline__ uint32_t smem_u32(const void* p) {
    uint32_t a;
    asm("{ .reg .u64 t; cvta.to.shared.u64 t, %1; cvt.u32.u64 %0, t; }"
        : "=r"(a) : "l"(p));
    return a;
}

__device__ __forceinline__ void cp16(uint32_t saddr, const void* gaddr) {
    asm volatile("cp.async.cg.shared.global [%0], [%1], 16;"
                 :: "r"(saddr), "l"(gaddr) : "memory");
}

__device__ __forceinline__ void cp_commit() {
    asm volatile("cp.async.commit_group;" ::: "memory");
}

__device__ __forceinline__ void cp_wait3() {
    asm volatile("cp.async.wait_group 3;" ::: "memory");
}

__device__ __forceinline__ uint32_t f2tf32(float f) {
    uint32_t r;
    asm("cvt.rna.tf32.f32 %0, %1;" : "=r"(r) : "f"(f));
    return r;
}

__device__ __forceinline__ void mma_tf32(float* c, const uint32_t* a,
                                         const uint32_t* b) {
    asm volatile(
        "mma.sync.aligned.m16n8k8.row.col.f32.tf32.tf32.f32 "
        "{%0,%1,%2,%3}, {%4,%5,%6,%7}, {%8,%9}, {%0,%1,%2,%3};"
        : "+f"(c[0]), "+f"(c[1]), "+f"(c[2]), "+f"(c[3])
        : "r"(a[0]), "r"(a[1]), "r"(a[2]), "r"(a[3]), "r"(b[0]), "r"(b[1]));
}

// ============================================================================
// Main GEMM
// ============================================================================
__global__ void __launch_bounds__(THREADS, 2) gemm_tf32(
    const float* __restrict__ x,
    const float* __restrict__ bias,
    float* __restrict__ out)
{
    extern __shared__ float smem[];
    const uint32_t sb = smem_u32(smem);
    const int tid = threadIdx.x;
    const int wid = tid >> 5;
    const int lane = tid & 31;
    const int grp = lane >> 2;     // 0..7
    const int qc = lane & 3;       // 0..3

    // bid -> tiles; consecutive bids share the M-tile (A reused in L2/SM wave)
    const int ntile = blockIdx.x & 7;           // 8 N-tiles of 64
    const int mtile = blockIdx.x >> 3;          // 512 M-tiles of 128
    const int m0 = mtile * BM;
    const int n0 = ntile * BN;

    const int warp_m = (wid & 3) * 32;          // 4 warps along M
    const int warp_n = (wid >> 2) * 32;         // 2 warps along N

    const float* wq = d_wq;

    // ---- cp.async tile loader ----
    auto load_stage = [&](int s, int kt) {
        const uint32_t sA = sb + s * STAGE_BYTES;
        const uint32_t sB = sA + A_STAGE_BYTES;
        const int kk = kt * BK;
        // A: 128 rows x 32 floats = 1024 x 16B chunks, 4 per thread
        #pragma unroll
        for (int i = 0; i < 4; i++) {
            int c = tid + i * THREADS;
            int row = c >> 3, cc = c & 7;
            cp16(sA + row * (PAD_K * 4) + cc * 16,
                 x + (size_t)(m0 + row) * K_DIM + kk + cc * 4);
        }
        // B: 64 rows x 32 floats = 512 chunks, 2 per thread
        #pragma unroll
        for (int i = 0; i < 2; i++) {
            int c = tid + i * THREADS;
            int row = c >> 3, cc = c & 7;
            cp16(sB + row * (PAD_K * 4) + cc * 16,
                 wq + (size_t)(n0 + row) * K_DIM + kk + cc * 4);
        }
    };

    float acc[2][4][4];
    #pragma unroll
    for (int i = 0; i < 2; i++)
        #pragma unroll
        for (int j = 0; j < 4; j++)
            #pragma unroll
            for (int r = 0; r < 4; r++) acc[i][j][r] = 0.0f;

    // prologue: fill STAGES-1 stages
    #pragma unroll
    for (int s = 0; s < STAGES - 1; s++) {
        load_stage(s, s);
        cp_commit();
    }

    for (int kt = 0; kt < KT; kt++) {
        if (kt + STAGES - 1 < KT) load_stage((kt + STAGES - 1) & 3, kt + STAGES - 1);
        cp_commit();                // empty group when nothing loaded (keeps count)
        cp_wait3();                 // stage kt now resident
        __syncthreads();

        const int s = kt & 3;
        const float* As = smem + s * (STAGE_BYTES / 4);
        const float* Bs = As + (A_STAGE_BYTES / 4);

        #pragma unroll
        for (int ks = 0; ks < 4; ks++) {   // four k=8 steps
            const int k0 = ks * 8;
            uint32_t a[2][4], b[4][2];
            #pragma unroll
            for (int tm = 0; tm < 2; tm++) {
                const float* ap = As + (warp_m + tm * 16 + grp) * PAD_K + k0 + qc;
                a[tm][0] = f2tf32(ap[0]);
                a[tm][1] = f2tf32(ap[8 * PAD_K]);
                a[tm][2] = f2tf32(ap[4]);
                a[tm][3] = f2tf32(ap[8 * PAD_K + 4]);
            }
            #pragma unroll
            for (int tn = 0; tn < 4; tn++) {
                const float* bp = Bs + (warp_n + tn * 8 + grp) * PAD_K + k0 + qc;
                b[tn][0] = __float_as_uint(bp[0]);   // S is exact, no cvt needed
                b[tn][1] = __float_as_uint(bp[4]);
            }
            #pragma unroll
            for (int tm = 0; tm < 2; tm++)
                #pragma unroll
                for (int tn = 0; tn < 4; tn++)
                    mma_tf32(acc[tm][tn], a[tm], b[tn]);
        }
        __syncthreads();
    }

    // ---- Epilogue: out = scale*acc + bias ----
    const float scale = d_scale;
    #pragma unroll
    for (int tm = 0; tm < 2; tm++) {
        #pragma unroll
        for (int tn = 0; tn < 4; tn++) {
            const int row = m0 + warp_m + tm * 16 + grp;
            const int col = n0 + warp_n + tn * 8 + qc * 2;
            const float2 bv = *reinterpret_cast<const float2*>(bias + col);
            float2 v0, v1;
            v0.x = fmaf(scale, acc[tm][tn][0], bv.x);
            v0.y = fmaf(scale, acc[tm][tn][1], bv.y);
            v1.x = fmaf(scale, acc[tm][tn][2], bv.x);
            v1.y = fmaf(scale, acc[tm][tn][3], bv.y);
            *reinterpret_cast<float2*>(out + (size_t)row * N_DIM + col) = v0;
            *reinterpret_cast<float2*>(out + (size_t)(row + 8) * N_DIM + col) = v1;
        }
    }
}

// ============================================================================
// Host
// ============================================================================
extern "C" void kernel_launch(void* const* d_in, const int* in_sizes, int n_in,
                              void* d_out, int out_size) {
    const float* x    = (const float*)d_in[0];
    const float* w    = (const float*)d_in[1];
    const float* bias = (const float*)d_in[2];
    float* out        = (float*)d_out;
    const int M = in_sizes[0] / K_DIM;   // 65536

    cudaFuncSetAttribute(gemm_tf32, cudaFuncAttributeMaxDynamicSharedMemorySize,
                         SMEM_TOTAL);

    k_abssum<<<256, 256>>>(w);
    k_scale<<<1, 1>>>();
    k_quant<<<(N_DIM * K_DIM) / 256, 256>>>(w);

    const int grid = (M / BM) * (N_DIM / BN);   // 512 * 8 = 4096
    gemm_tf32<<<grid, THREADS, SMEM_TOTAL>>>(x, bias, out);
}

// round 3
// speedup vs baseline: 1.1008x; 1.1008x over previous
#include <cuda_runtime.h>
#include <cstdint>

// ============================================================================
// QuantizedLinear: out = scale * (x @ S^T) + bias, S = sign(w)*(|w|>0.7*mean|w|)
// x [65536, 512] fp32, w [512, 512] fp32, bias [512] fp32, out [65536, 512] fp32
//
// Toolchain: PTX targets compute_103 (non-'a') -> no tcgen05/TMEM. Use
// mma.sync.m16n8k8.tf32 + cp.async multistage, warp tile 64x32.
// ============================================================================
#define K_DIM 512
#define N_DIM 512
#define BM 128
#define BN 128
#define BK 32
#define KT (K_DIM / BK)      // 16
#define STAGES 3
#define PAD_K 36             // 32 + 4 pad -> conflict-free scalar LDS
#define THREADS 256

#define A_STAGE_BYTES (BM * PAD_K * 4)           // 18432
#define B_STAGE_BYTES (BN * PAD_K * 4)           // 18432
#define STAGE_BYTES   (A_STAGE_BYTES + B_STAGE_BYTES)
#define SMEM_TOTAL    (STAGES * STAGE_BYTES)     // 110592 -> 2 CTAs/SM

// Scratch (allocation-free)
__device__ float  d_wq[N_DIM * K_DIM];
__device__ double d_partial[256];
__device__ float  d_scale;
__device__ float  d_thresh;

// ============================================================================
// Prep kernels
// ============================================================================
__global__ void k_abssum(const float* __restrict__ w) {
    __shared__ double s[256];
    int b = blockIdx.x, t = threadIdx.x;
    const float* p = w + b * 1024;
    double acc = (double)fabsf(p[t]) + (double)fabsf(p[t + 256]) +
                 (double)fabsf(p[t + 512]) + (double)fabsf(p[t + 768]);
    s[t] = acc;
    __syncthreads();
    for (int o = 128; o > 0; o >>= 1) {
        if (t < o) s[t] += s[t + o];
        __syncthreads();
    }
    if (t == 0) d_partial[b] = s[0];
}

__global__ void k_scale() {
    double tot = 0.0;
    for (int i = 0; i < 256; i++) tot += d_partial[i];
    float sc = (float)(tot / (double)(N_DIM * K_DIM));
    if (sc < 1e-8f) sc = 1e-8f;
    d_scale = sc;
    d_thresh = 0.7f * sc;
}

__global__ void k_quant(const float* __restrict__ w) {
    int i = blockIdx.x * blockDim.x + threadIdx.x;
    float v = w[i];
    float th = d_thresh;
    d_wq[i] = (fabsf(v) > th) ? (v > 0.0f ? 1.0f : -1.0f) : 0.0f;
}

// ============================================================================
// Helpers
// ============================================================================
__device__ __forceinline__ uint32_t smem_u32(const void* p) {
    uint32_t a;
    asm("{ .reg .u64 t; cvta.to.shared.u64 t, %1; cvt.u32.u64 %0, t; }"
        : "=r"(a) : "l"(p));
    return a;
}

__device__ __forceinline__ void cp16(uint32_t saddr, const void* gaddr) {
    asm volatile("cp.async.cg.shared.global [%0], [%1], 16;"
                 :: "r"(saddr), "l"(gaddr) : "memory");
}

__device__ __forceinline__ void cp_commit() {
    asm volatile("cp.async.commit_group;" ::: "memory");
}

__device__ __forceinline__ void cp_wait1() {
    asm volatile("cp.async.wait_group 1;" ::: "memory");
}

__device__ __forceinline__ uint32_t f2tf32(float f) {
    uint32_t r;
    asm("cvt.rna.tf32.f32 %0, %1;" : "=r"(r) : "f"(f));
    return r;
}

__device__ __forceinline__ void mma_tf32(float* c, const uint32_t* a,
                                         const uint32_t* b) {
    asm volatile(
        "mma.sync.aligned.m16n8k8.row.col.f32.tf32.tf32.f32 "
        "{%0,%1,%2,%3}, {%4,%5,%6,%7}, {%8,%9}, {%0,%1,%2,%3};"
        : "+f"(c[0]), "+f"(c[1]), "+f"(c[2]), "+f"(c[3])
        : "r"(a[0]), "r"(a[1]), "r"(a[2]), "r"(a[3]), "r"(b[0]), "r"(b[1]));
}

// ============================================================================
// Main GEMM: block 128x128, 8 warps, warp tile 64x32 (2M x 4N warp grid)
// ============================================================================
__global__ void __launch_bounds__(THREADS, 2) gemm_tf32(
    const float* __restrict__ x,
    const float* __restrict__ bias,
    float* __restrict__ out)
{
    extern __shared__ float smem[];
    const uint32_t sb = smem_u32(smem);
    const int tid = threadIdx.x;
    const int wid = tid >> 5;
    const int lane = tid & 31;
    const int grp = lane >> 2;     // 0..7
    const int qc = lane & 3;       // 0..3

    // 4 N-tiles x 512 M-tiles; consecutive bids share the M-tile (A L2 reuse)
    const int ntile = blockIdx.x & 3;
    const int mtile = blockIdx.x >> 2;
    const int m0 = mtile * BM;
    const int n0 = ntile * BN;

    const int warp_m = (wid & 1) * 64;          // 2 warps along M (64 rows)
    const int warp_n = (wid >> 1) * 32;         // 4 warps along N (32 cols)

    const float* wq = d_wq;

    // ---- cp.async tile loader: 2048 16B chunks / 256 threads = 8 each ----
    auto load_stage = [&](int s, int kt) {
        const uint32_t sA = sb + s * STAGE_BYTES;
        const uint32_t sB = sA + A_STAGE_BYTES;
        const int kk = kt * BK;
        #pragma unroll
        for (int i = 0; i < 4; i++) {
            int c = tid + i * THREADS;
            int row = c >> 3, cc = c & 7;
            cp16(sA + row * (PAD_K * 4) + cc * 16,
                 x + (size_t)(m0 + row) * K_DIM + kk + cc * 4);
        }
        #pragma unroll
        for (int i = 0; i < 4; i++) {
            int c = tid + i * THREADS;
            int row = c >> 3, cc = c & 7;
            cp16(sB + row * (PAD_K * 4) + cc * 16,
                 wq + (size_t)(n0 + row) * K_DIM + kk + cc * 4);
        }
    };

    float acc[4][4][4];
    #pragma unroll
    for (int i = 0; i < 4; i++)
        #pragma unroll
        for (int j = 0; j < 4; j++)
            #pragma unroll
            for (int r = 0; r < 4; r++) acc[i][j][r] = 0.0f;

    // prologue: stages 0,1
    load_stage(0, 0);
    cp_commit();
    load_stage(1, 1);
    cp_commit();

    for (int kt = 0; kt < KT; kt++) {
        cp_wait1();                 // stage kt resident
        __syncthreads();            // all warps see it; slot (kt+2)%3 free

        if (kt + 2 < KT) load_stage((kt + 2) % STAGES, kt + 2);
        cp_commit();                // one group per iteration (may be empty)

        const int s = kt % STAGES;
        const float* As = smem + s * (STAGE_BYTES / 4);
        const float* Bs = As + (A_STAGE_BYTES / 4);

        #pragma unroll
        for (int ks = 0; ks < 4; ks++) {   // four k=8 steps
            const int k0 = ks * 8;
            uint32_t a[4][4], b[4][2];
            #pragma unroll
            for (int tm = 0; tm < 4; tm++) {
                const float* ap = As + (warp_m + tm * 16 + grp) * PAD_K + k0 + qc;
                a[tm][0] = f2tf32(ap[0]);
                a[tm][1] = f2tf32(ap[8 * PAD_K]);
                a[tm][2] = f2tf32(ap[4]);
                a[tm][3] = f2tf32(ap[8 * PAD_K + 4]);
            }
            #pragma unroll
            for (int tn = 0; tn < 4; tn++) {
                const float* bp = Bs + (warp_n + tn * 8 + grp) * PAD_K + k0 + qc;
                b[tn][0] = __float_as_uint(bp[0]);   // S exact in tf32
                b[tn][1] = __float_as_uint(bp[4]);
            }
            #pragma unroll
            for (int tm = 0; tm < 4; tm++)
                #pragma unroll
                for (int tn = 0; tn < 4; tn++)
                    mma_tf32(acc[tm][tn], a[tm], b[tn]);
        }
    }

    // ---- Epilogue: out = scale*acc + bias ----
    const float scale = d_scale;
    #pragma unroll
    for (int tm = 0; tm < 4; tm++) {
        #pragma unroll
        for (int tn = 0; tn < 4; tn++) {
            const int row = m0 + warp_m + tm * 16 + grp;
            const int col = n0 + warp_n + tn * 8 + qc * 2;
            const float2 bv = *reinterpret_cast<const float2*>(bias + col);
            float2 v0, v1;
            v0.x = fmaf(scale, acc[tm][tn][0], bv.x);
            v0.y = fmaf(scale, acc[tm][tn][1], bv.y);
            v1.x = fmaf(scale, acc[tm][tn][2], bv.x);
            v1.y = fmaf(scale, acc[tm][tn][3], bv.y);
            *reinterpret_cast<float2*>(out + (size_t)row * N_DIM + col) = v0;
            *reinterpret_cast<float2*>(out + (size_t)(row + 8) * N_DIM + col) = v1;
        }
    }
}

// ============================================================================
// Host
// ============================================================================
extern "C" void kernel_launch(void* const* d_in, const int* in_sizes, int n_in,
                              void* d_out, int out_size) {
    const float* x    = (const float*)d_in[0];
    const float* w    = (const float*)d_in[1];
    const float* bias = (const float*)d_in[2];
    float* out        = (float*)d_out;
    const int M = in_sizes[0] / K_DIM;   // 65536

    cudaFuncSetAttribute(gemm_tf32, cudaFuncAttributeMaxDynamicSharedMemorySize,
                         SMEM_TOTAL);

    k_abssum<<<256, 256>>>(w);
    k_scale<<<1, 1>>>();
    k_quant<<<(N_DIM * K_DIM) / 256, 256>>>(w);

    const int grid = (M / BM) * (N_DIM / BN);   // 512 * 4 = 2048
    gemm_tf32<<<grid, THREADS, SMEM_TOTAL>>>(x, bias, out);
}